// round 11
// baseline (speedup 1.0000x reference)
#include <cuda_runtime.h>
#include <cuda_fp16.h>
#include <cstdint>

#define PPIX 3136
#define CH 256
#define DIM 32
#define KER 7
#define K2 49
#define TILE 14
#define HALO 20
#define HALOSZ 400
#define HROW 40     // halfs per halo row (32 ch + pad), 80B, 16B-aligned
#define SROW 50     // floats per score row (49 + pad)

// scratch (allocation-free rule: device globals)
__device__ __align__(16) float g_Qp[2 * PPIX * CH];
__device__ __align__(16) float g_Kp[2 * PPIX * CH];
__device__ __align__(16) float g_Vp[2 * PPIX * CH];
__device__ __align__(16) float g_O [2 * PPIX * CH];
__device__ __align__(16) float g_Wt[4 * CH * CH];     // tf32-rounded Wq,Wk,Wv,Wout
__device__ __align__(16) float g_bcv[CH];

// ---------------------------------------------------------------------------
// helpers
// ---------------------------------------------------------------------------
__device__ __forceinline__ uint32_t f2tf(float x) {
    uint32_t r;
    asm("cvt.rna.tf32.f32 %0, %1;" : "=r"(r) : "f"(x));
    return r;
}
__device__ __forceinline__ float f2tf_f(float x) { return __uint_as_float(f2tf(x)); }
__device__ __forceinline__ void mma_tf32(float c[4], const uint32_t a[4], const uint32_t b[2]) {
    asm volatile(
        "mma.sync.aligned.m16n8k8.row.col.f32.tf32.tf32.f32 "
        "{%0,%1,%2,%3}, {%4,%5,%6,%7}, {%8,%9}, {%0,%1,%2,%3};"
        : "+f"(c[0]), "+f"(c[1]), "+f"(c[2]), "+f"(c[3])
        : "r"(a[0]), "r"(a[1]), "r"(a[2]), "r"(a[3]), "r"(b[0]), "r"(b[1]));
}
__device__ __forceinline__ void cp16(float* smem_dst, const float* gmem_src) {
    uint32_t s = (uint32_t)__cvta_generic_to_shared(smem_dst);
    asm volatile("cp.async.cg.shared.global [%0], [%1], 16;" :: "r"(s), "l"(gmem_src));
}
#define CP_COMMIT()  asm volatile("cp.async.commit_group;")
#define CP_WAIT1()   asm volatile("cp.async.wait_group 1;")
#define CP_WAIT0()   asm volatile("cp.async.wait_group 0;")

#define PROJ_STG (5 * 2304)   // A_q[32][72] + A_k[32][72] + 3x B[64][36] (floats)
#define OUT_STG  (3 * 2304)   // A0[64][36] + A1[64][36] + B[64][36]

// ---------------------------------------------------------------------------
// tf32-round all weights into g_Wt:  [0..3*CH*CH) = in_proj, then out_proj
// ---------------------------------------------------------------------------
__global__ void w_tf32_kernel(const float* __restrict__ ipw, const float* __restrict__ opw) {
    int i = blockIdx.x * 128 + threadIdx.x;            // float4 index, 65536 total
    const int IPW4 = 3 * CH * CH / 4;                   // 49152
    float4 v = (i < IPW4) ? reinterpret_cast<const float4*>(ipw)[i]
                          : reinterpret_cast<const float4*>(opw)[i - IPW4];
    v.x = f2tf_f(v.x); v.y = f2tf_f(v.y); v.z = f2tf_f(v.z); v.w = f2tf_f(v.w);
    reinterpret_cast<float4*>(g_Wt)[i] = v;
}

// ---------------------------------------------------------------------------
// bcv[c'] = pos * sum_c Wv[c'][c] + bv[c']   (V block only; K-side bias
// cancels exactly in softmax)
// ---------------------------------------------------------------------------
__global__ void bconst_kernel(const float* __restrict__ W, const float* __restrict__ b,
                              const float* __restrict__ pos) {
    int c = blockIdx.x * 8 + (threadIdx.x >> 5);
    int lane = threadIdx.x & 31;
    float p = pos[0];
    const float4* wv = reinterpret_cast<const float4*>(W + (size_t)(2 * CH + c) * CH);
    float4 v0 = wv[lane * 2], v1 = wv[lane * 2 + 1];
    float sv = v0.x + v0.y + v0.z + v0.w + v1.x + v1.y + v1.z + v1.w;
    #pragma unroll
    for (int o = 16; o > 0; o >>= 1)
        sv += __shfl_xor_sync(0xffffffffu, sv, o);
    if (lane == 0)
        g_bcv[c] = p * sv + b[2 * CH + c];
}

// ---------------------------------------------------------------------------
// Fused Q/K/V projection (tf32, BM=64 BN=64 BK=32, cp.async 2-stage,
// 256 threads / 8 warps as 4m x 2n (warp tile 16x32), 2 CTAs/SM = 16 warps).
// Stage: A_q | A_k (k-major [32][72]) | B_q | B_k | B_v (n-major [64][36]).
// blockIdx.z = n
// ---------------------------------------------------------------------------
__global__ void __launch_bounds__(256, 2)
proj_gemm(const float* __restrict__ queries, const float* __restrict__ key,
          const float* __restrict__ bvec) {
    int n = blockIdx.z;
    const float* InQ = queries + (size_t)n * CH * PPIX;
    const float* InK = key     + (size_t)n * CH * PPIX;

    extern __shared__ float smf[];     // [2][PROJ_STG]

    int tid = threadIdx.x;
    int m0 = blockIdx.x * 64;
    int c0 = blockIdx.y * 64;
    int w = tid >> 5, lane = tid & 31;
    int r = lane >> 2, tig = lane & 3;
    int wm = (w & 3) * 16;             // 4 m-warps
    int wn = (w >> 2) * 32;            // 2 n-warps

    float acc[3][4][4] = {};

    auto issue5 = [&](int t) {
        float* base = smf + (t & 1) * PROJ_STG;
        int kt = t * 32;
        #pragma unroll
        for (int i = 0; i < 2; i++) {
            int id = tid + 256 * i;
            int row = id >> 4;                 // 0..31
            int c4 = (id & 15) * 4;            // 0..60
            cp16(base + row * 72 + c4,        InQ + (size_t)(kt + row) * PPIX + m0 + c4);
            cp16(base + 2304 + row * 72 + c4, InK + (size_t)(kt + row) * PPIX + m0 + c4);
        }
        #pragma unroll
        for (int pr = 0; pr < 3; pr++) {
            const float* W = g_Wt + (size_t)pr * CH * CH;
            float* Bs = base + 2 * 2304 + pr * 2304;
            #pragma unroll
            for (int i = 0; i < 2; i++) {
                int id = tid + 256 * i;
                int row = id >> 3;             // 0..63
                int k4 = (id & 7) * 4;         // 0..28
                cp16(Bs + row * 36 + k4, W + (size_t)(c0 + row) * CH + kt + k4);
            }
        }
        CP_COMMIT();
    };

    issue5(0);

    for (int it = 0; it < 8; it++) {
        if (it + 1 < 8) { issue5(it + 1); CP_WAIT1(); }
        else            { CP_WAIT0(); }
        __syncthreads();

        const float* base = smf + (it & 1) * PROJ_STG;
        #pragma unroll
        for (int ks = 0; ks < 4; ks++) {
            int k0 = ks * 8;
            uint32_t aq[4], ak[4];
            {
                int m = wm + r;
                aq[0] = f2tf(base[(k0 + tig) * 72 + m]);
                aq[1] = f2tf(base[(k0 + tig) * 72 + m + 8]);
                aq[2] = f2tf(base[(k0 + tig + 4) * 72 + m]);
                aq[3] = f2tf(base[(k0 + tig + 4) * 72 + m + 8]);
                ak[0] = f2tf(base[2304 + (k0 + tig) * 72 + m]);
                ak[1] = f2tf(base[2304 + (k0 + tig) * 72 + m + 8]);
                ak[2] = f2tf(base[2304 + (k0 + tig + 4) * 72 + m]);
                ak[3] = f2tf(base[2304 + (k0 + tig + 4) * 72 + m + 8]);
            }
            #pragma unroll
            for (int pr = 0; pr < 3; pr++) {
                const float* Bb = base + 2 * 2304 + pr * 2304;
                uint32_t b[4][2];
                #pragma unroll
                for (int nt = 0; nt < 4; nt++) {
                    int nn = wn + nt * 8 + r;
                    b[nt][0] = __float_as_uint(Bb[nn * 36 + k0 + tig]);
                    b[nt][1] = __float_as_uint(Bb[nn * 36 + k0 + tig + 4]);
                }
                #pragma unroll
                for (int nt = 0; nt < 4; nt++)
                    mma_tf32(acc[pr][nt], (pr == 0) ? aq : ak, b[nt]);
            }
        }
        __syncthreads();
    }

    float* Outs[3] = { g_Qp + (size_t)n * PPIX * CH,
                       g_Kp + (size_t)n * PPIX * CH,
                       g_Vp + (size_t)n * PPIX * CH };
    #pragma unroll
    for (int pr = 0; pr < 3; pr++) {
        float* Out = Outs[pr];
        int row0 = m0 + wm + r;
        #pragma unroll
        for (int nt = 0; nt < 4; nt++) {
            int cc = c0 + wn + nt * 8 + 2 * tig;
            float b0 = (pr == 0) ? bvec[cc] : 0.f;
            float b1 = (pr == 0) ? bvec[cc + 1] : 0.f;
            *reinterpret_cast<float2*>(Out + (size_t)row0 * CH + cc) =
                make_float2(acc[pr][nt][0] + b0, acc[pr][nt][1] + b1);
            *reinterpret_cast<float2*>(Out + (size_t)(row0 + 8) * CH + cc) =
                make_float2(acc[pr][nt][2] + b0, acc[pr][nt][3] + b1);
        }
    }
}

// ---------------------------------------------------------------------------
// Local attention: thread PAIR per pixel (16 channels each), 512 threads,
// fp16 K/V halos + f32 score rows in smem, 2 CTAs/SM.
// ---------------------------------------------------------------------------
__global__ void __launch_bounds__(512, 2) attn_kernel() {
    extern __shared__ char smraw[];
    __half* Ks = reinterpret_cast<__half*>(smraw);
    __half* Vs = Ks + HALOSZ * HROW;
    float*  Ssc = reinterpret_cast<float*>(smraw + 2 * HALOSZ * HROW * sizeof(__half));

    int tx0 = blockIdx.x * TILE;
    int ty0 = blockIdx.y * TILE;
    int h = blockIdx.z & 7;
    int n = blockIdx.z >> 3;
    int tid = threadIdx.x;
    int cbase = h * DIM;

    const float* Kp = g_Kp + (size_t)n * PPIX * CH;
    const float* Vp = g_Vp + (size_t)n * PPIX * CH;

    for (int idx = tid; idx < HALOSZ * 4 * 2; idx += 512) {
        int m = idx >= HALOSZ * 4;
        int j = m ? idx - HALOSZ * 4 : idx;
        int hp = j >> 2;
        int c8 = (j & 3) * 8;
        int gy = ty0 - 3 + hp / HALO;
        int gx = tx0 - 3 + hp % HALO;
        float4 a = make_float4(0.f, 0.f, 0.f, 0.f);
        float4 b = make_float4(0.f, 0.f, 0.f, 0.f);
        if (gy >= 0 && gy < 56 && gx >= 0 && gx < 56) {
            const float* src = (m ? Vp : Kp) + (size_t)(gy * 56 + gx) * CH + cbase + c8;
            a = *reinterpret_cast<const float4*>(src);
            b = *reinterpret_cast<const float4*>(src + 4);
        }
        __half2 hh[4];
        hh[0] = __floats2half2_rn(a.x, a.y);
        hh[1] = __floats2half2_rn(a.z, a.w);
        hh[2] = __floats2half2_rn(b.x, b.y);
        hh[3] = __floats2half2_rn(b.z, b.w);
        *reinterpret_cast<uint4*>((m ? Vs : Ks) + hp * HROW + c8) =
            *reinterpret_cast<uint4*>(hh);
    }
    __syncthreads();

    if (tid >= 2 * TILE * TILE) return;
    int pix = tid >> 1;
    int half = tid & 1;
    unsigned msk = (tid < 384) ? 0xffffffffu : 0xffu;
    int ly = pix / TILE, lx = pix % TILE;
    int p = (ty0 + ly) * 56 + (tx0 + lx);
    int coff = half * 16;
    float* srow = Ssc + pix * SROW;

    const float scale = 0.17677669529663687f;
    float2 q2[8];
    {
        const float* qptr = g_Qp + (size_t)n * PPIX * CH + (size_t)p * CH + cbase + coff;
        #pragma unroll
        for (int i = 0; i < 4; i++) {
            float4 v = *reinterpret_cast<const float4*>(qptr + i * 4);
            q2[2 * i]     = make_float2(v.x * scale, v.y * scale);
            q2[2 * i + 1] = make_float2(v.z * scale, v.w * scale);
        }
    }

    float mx = -1e30f;
    #pragma unroll
    for (int ti = 0; ti < KER; ti++) {
        #pragma unroll
        for (int tj = 0; tj < KER; tj++) {
            const __half* kr = Ks + ((ly + ti) * HALO + (lx + tj)) * HROW + coff;
            __half2 hh[8];
            *reinterpret_cast<uint4*>(hh)     = *reinterpret_cast<const uint4*>(kr);
            *reinterpret_cast<uint4*>(hh + 4) = *reinterpret_cast<const uint4*>(kr + 8);
            float s0 = 0.f, s1 = 0.f;
            #pragma unroll
            for (int i = 0; i < 8; i++) {
                float2 f = __half22float2(hh[i]);
                s0 += q2[i].x * f.x;
                s1 += q2[i].y * f.y;
            }
            float s = s0 + s1;
            s += __shfl_xor_sync(msk, s, 1);
            if (half == 0) srow[ti * KER + tj] = s;
            mx = fmaxf(mx, s);
        }
    }
    __syncwarp(msk);

    float sum = 0.f;
    #pragma unroll
    for (int t = 0; t < K2; t++) {
        float wgt = __expf(srow[t] - mx);
        sum += wgt;
        if (half == 0) srow[t] = wgt;
    }
    __syncwarp(msk);
    float inv = 1.f / sum;

    float2 o2[8];
    #pragma unroll
    for (int i = 0; i < 8; i++) o2[i] = make_float2(0.f, 0.f);
    #pragma unroll
    for (int ti = 0; ti < KER; ti++) {
        #pragma unroll
        for (int tj = 0; tj < KER; tj++) {
            const __half* vr = Vs + ((ly + ti) * HALO + (lx + tj)) * HROW + coff;
            __half2 hh[8];
            *reinterpret_cast<uint4*>(hh)     = *reinterpret_cast<const uint4*>(vr);
            *reinterpret_cast<uint4*>(hh + 4) = *reinterpret_cast<const uint4*>(vr + 8);
            float wgt = srow[ti * KER + tj];
            #pragma unroll
            for (int i = 0; i < 8; i++) {
                float2 f = __half22float2(hh[i]);
                o2[i].x += wgt * f.x;
                o2[i].y += wgt * f.y;
            }
        }
    }

    float* optr = g_O + (size_t)n * PPIX * CH + (size_t)p * CH + cbase + coff;
    #pragma unroll
    for (int i = 0; i < 4; i++) {
        float4 bc = *reinterpret_cast<const float4*>(g_bcv + cbase + coff + i * 4);
        float4 t;
        t.x = f2tf_f(o2[2 * i].x     * inv + bc.x);
        t.y = f2tf_f(o2[2 * i].y     * inv + bc.y);
        t.z = f2tf_f(o2[2 * i + 1].x * inv + bc.z);
        t.w = f2tf_f(o2[2 * i + 1].y * inv + bc.w);
        *reinterpret_cast<float4*>(optr + i * 4) = t;
    }
}

// ---------------------------------------------------------------------------
// Out projection, both batches fused (tf32, BM=64 BN=64 BK=32, cp.async
// 2-stage, 256 threads / 8 warps as 4m x 2n (warp tile 16x32), 3 CTAs/SM).
// No cvts (inputs already tf32-rounded).
// ---------------------------------------------------------------------------
__global__ void __launch_bounds__(256, 3)
outproj_gemm(const float* __restrict__ bout, float* __restrict__ out) {
    extern __shared__ float smf[];     // [2][OUT_STG]
    const float* Wout = g_Wt + 3 * CH * CH;

    int tid = threadIdx.x;
    int m0 = blockIdx.x * 64;
    int c0 = blockIdx.y * 64;
    int w = tid >> 5, lane = tid & 31;
    int r = lane >> 2, tig = lane & 3;
    int wm = (w & 3) * 16;
    int wn = (w >> 2) * 32;

    float acc[2][4][4] = {};

    auto issue_tile = [&](int t) {
        float* base = smf + (t & 1) * OUT_STG;
        int kt = t * 32;
        #pragma unroll
        for (int i = 0; i < 2; i++) {
            int id = tid + 256 * i;
            int row = id >> 3;                 // 0..63
            int k4 = (id & 7) * 4;
            cp16(base + row * 36 + k4,
                 g_O + (size_t)(m0 + row) * CH + kt + k4);
            cp16(base + 2304 + row * 36 + k4,
                 g_O + (size_t)PPIX * CH + (size_t)(m0 + row) * CH + kt + k4);
            cp16(base + 4608 + row * 36 + k4,
                 Wout + (size_t)(c0 + row) * CH + kt + k4);
        }
        CP_COMMIT();
    };

    issue_tile(0);

    for (int it = 0; it < 8; it++) {
        if (it + 1 < 8) { issue_tile(it + 1); CP_WAIT1(); }
        else            { CP_WAIT0(); }
        __syncthreads();

        const float* base = smf + (it & 1) * OUT_STG;
        #pragma unroll
        for (int ks = 0; ks < 4; ks++) {
            int k0 = ks * 8;
            uint32_t a[2][4], b[4][2];
            #pragma unroll
            for (int nb = 0; nb < 2; nb++) {
                const float* Ab = base + nb * 2304;
                int m = wm + r;
                a[nb][0] = __float_as_uint(Ab[m * 36 + k0 + tig]);
                a[nb][1] = __float_as_uint(Ab[(m + 8) * 36 + k0 + tig]);
                a[nb][2] = __float_as_uint(Ab[m * 36 + k0 + tig + 4]);
                a[nb][3] = __float_as_uint(Ab[(m + 8) * 36 + k0 + tig + 4]);
            }
            #pragma unroll
            for (int nt = 0; nt < 4; nt++) {
                int nn = wn + nt * 8 + r;
                b[nt][0] = __float_as_uint(base[4608 + nn * 36 + k0 + tig]);
                b[nt][1] = __float_as_uint(base[4608 + nn * 36 + k0 + tig + 4]);
            }
            #pragma unroll
            for (int nb = 0; nb < 2; nb++)
                #pragma unroll
                for (int nt = 0; nt < 4; nt++)
                    mma_tf32(acc[nb][nt], a[nb], b[nt]);
        }
        __syncthreads();
    }

    #pragma unroll
    for (int nb = 0; nb < 2; nb++) {
        float* ob = out + (size_t)nb * CH * PPIX;
        int row0 = m0 + wm + r;
        #pragma unroll
        for (int nt = 0; nt < 4; nt++) {
            int cc = c0 + wn + nt * 8 + 2 * tig;
            float b0 = bout[cc], b1 = bout[cc + 1];
            ob[(size_t)cc * PPIX + row0]           = acc[nb][nt][0] + b0;
            ob[(size_t)(cc + 1) * PPIX + row0]     = acc[nb][nt][1] + b1;
            ob[(size_t)cc * PPIX + row0 + 8]       = acc[nb][nt][2] + b0;
            ob[(size_t)(cc + 1) * PPIX + row0 + 8] = acc[nb][nt][3] + b1;
        }
    }
}

extern "C" void kernel_launch(void* const* d_in, const int* in_sizes, int n_in,
                              void* d_out, int out_size) {
    const float* queries = (const float*)d_in[0];
    const float* key     = (const float*)d_in[1];
    const float* pos     = (const float*)d_in[2];
    const float* ipw     = (const float*)d_in[3];
    const float* ipb     = (const float*)d_in[4];
    const float* opw     = (const float*)d_in[5];
    const float* opb     = (const float*)d_in[6];
    float* out = (float*)d_out;

    const int proj_smem = 2 * PROJ_STG * (int)sizeof(float);        // 92160
    const int outp_smem = 2 * OUT_STG * (int)sizeof(float);         // 55296
    const int attn_smem = 2 * HALOSZ * HROW * (int)sizeof(__half)
                        + TILE * TILE * SROW * (int)sizeof(float);  // 103200

    cudaFuncSetAttribute(proj_gemm,    cudaFuncAttributeMaxDynamicSharedMemorySize, proj_smem);
    cudaFuncSetAttribute(outproj_gemm, cudaFuncAttributeMaxDynamicSharedMemorySize, outp_smem);
    cudaFuncSetAttribute(attn_kernel,  cudaFuncAttributeMaxDynamicSharedMemorySize, attn_smem);

    w_tf32_kernel<<<512, 128>>>(ipw, opw);
    bconst_kernel<<<32, 256>>>(ipw, ipb, pos);
    proj_gemm<<<dim3(49, 4, 2), 256, proj_smem>>>(queries, key, ipb);
    attn_kernel<<<dim3(4, 4, 16), 512, attn_smem>>>();
    outproj_gemm<<<dim3(49, 4, 1), 256, outp_smem>>>(opb, out);
}